// round 6
// baseline (speedup 1.0000x reference)
#include <cuda_runtime.h>

#define CONCEPTS 128
#define MM 14          // nb_mod_max + 2
#define DC 128         // concept dim
#define DIN 3

// Per-concept Gram G = W[c] W[c]^T, padded to 8 floats: {G00,G01,G02,G11,G12,G22,_,_}
__device__ float g_G[CONCEPTS * 8];

// ---------------------------------------------------------------------------
// G[c] = W[c] W[c]^T. One warp per concept.
// ---------------------------------------------------------------------------
__global__ void gmat_kernel(const float* __restrict__ W) {
    int c = blockIdx.x;
    int lane = threadIdx.x;
    const float4* w = reinterpret_cast<const float4*>(W + (size_t)c * DIN * DC);
    float4 a = w[lane];
    float4 b = w[32 + lane];
    float4 d = w[64 + lane];
    float s[6];
    s[0] = a.x*a.x + a.y*a.y + a.z*a.z + a.w*a.w;
    s[1] = a.x*b.x + a.y*b.y + a.z*b.z + a.w*b.w;
    s[2] = a.x*d.x + a.y*d.y + a.z*d.z + a.w*d.w;
    s[3] = b.x*b.x + b.y*b.y + b.z*b.z + b.w*b.w;
    s[4] = b.x*d.x + b.y*d.y + b.z*d.z + b.w*d.w;
    s[5] = d.x*d.x + d.y*d.y + d.z*d.z + d.w*d.w;
    #pragma unroll
    for (int off = 16; off; off >>= 1)
        #pragma unroll
        for (int k = 0; k < 6; k++)
            s[k] += __shfl_xor_sync(0xffffffffu, s[k], off);
    if (lane == 0) {
        #pragma unroll
        for (int k = 0; k < 6; k++) g_G[c * 8 + k] = s[k];
        g_G[c * 8 + 6] = 0.0f;
        g_G[c * 8 + 7] = 0.0f;
    }
}

// ---------------------------------------------------------------------------
// 8 rows per warp; 4 lanes per row (sub = lane&3 owns channels [32*sub, 32*sub+32)).
//   - dot products accumulated over 8 float4 chunks per lane
//   - v all-reduce: 2-stage butterfly within the 4-lane group
//   - each lane scores modalities m = sub, sub+4, sub+8, sub+12 (serial, FMA pipe)
//   - 2-stage lexicographic (value,index) argmin -> first-min index (jnp.argmin)
// ---------------------------------------------------------------------------
__global__ void __launch_bounds__(256) impact_kernel(
    const int*   __restrict__ user_ids,
    const int*   __restrict__ item_ids,
    const int*   __restrict__ concept_ids,
    const float* __restrict__ uemb,     // (USER_N, 128)
    const float* __restrict__ irw,      // (ITEM_N*14, 3)
    const float* __restrict__ W,        // (128, 3, 128)
    const float* __restrict__ maskt,    // (ITEM_N, 14)
    const int*   __restrict__ nbmod,    // (ITEM_N,)
    float*       __restrict__ out,
    int nrows)
{
    const unsigned FULL = 0xffffffffu;
    int warp = (int)((blockIdx.x * blockDim.x + threadIdx.x) >> 5);
    int lane = threadIdx.x & 31;
    int sub  = lane & 3;        // position within 4-lane row group

    long row = (long)warp * 8 + (lane >> 2);
    bool active = row < nrows;
    long ridx = active ? row : 0;

    int uid = user_ids[ridx];
    int it  = item_ids[ridx];
    int cc  = concept_ids[ridx];

    const float* ub = uemb + (size_t)uid * DC + sub * 32;
    const float* wb = W + (size_t)cc * DIN * DC + sub * 32;

    // ---- dot products over this lane's 32 channels (8 float4 chunks) ----
    float v0 = 0.f, v1 = 0.f, v2 = 0.f;
    #pragma unroll
    for (int k = 0; k < 8; k++) {
        float4 u4 = *reinterpret_cast<const float4*>(ub + 4 * k);
        float4 a0 = *reinterpret_cast<const float4*>(wb + 4 * k);
        float4 a1 = *reinterpret_cast<const float4*>(wb + DC + 4 * k);
        float4 a2 = *reinterpret_cast<const float4*>(wb + 2 * DC + 4 * k);
        v0 += u4.x*a0.x + u4.y*a0.y + u4.z*a0.z + u4.w*a0.w;
        v1 += u4.x*a1.x + u4.y*a1.y + u4.z*a1.z + u4.w*a1.w;
        v2 += u4.x*a2.x + u4.y*a2.y + u4.z*a2.z + u4.w*a2.w;
    }

    // ---- 2-stage all-reduce within the 4-lane group ----
    #pragma unroll
    for (int off = 1; off <= 2; off <<= 1) {
        v0 += __shfl_xor_sync(FULL, v0, off);
        v1 += __shfl_xor_sync(FULL, v1, off);
        v2 += __shfl_xor_sync(FULL, v2, off);
    }

    // ---- per-row Gram (broadcast load within group) ----
    const float4* Gp = reinterpret_cast<const float4*>(g_G + cc * 8);
    float4 Ga = __ldg(Gp);        // G00 G01 G02 G11
    float4 Gb = __ldg(Gp + 1);    // G12 G22 _ _

    // ---- score this lane's modalities: m = sub + 4j, ascending ----
    float best = __int_as_float(0x7f800000);
    int   bi   = MM;  // sentinel > any valid index
    const float* ebase = irw + (size_t)it * MM * DIN;
    const float* mbase = maskt + (size_t)it * MM;
    #pragma unroll
    for (int j = 0; j < 4; j++) {
        int m = sub + 4 * j;
        if (m < MM) {
            const float* e = ebase + m * DIN;
            float e0 = e[0], e1 = e[1], e2 = e[2];
            float q = e0*e0*Ga.x + e1*e1*Ga.w + e2*e2*Gb.y
                    + 2.0f*(e0*e1*Ga.y + e0*e2*Ga.z + e1*e2*Gb.x);
            float s = q - 2.0f*(e0*v0 + e1*v1 + e2*v2) + mbase[m];
            if (s < best) { best = s; bi = m; }   // strict <: keeps earliest m
        }
    }

    // ---- 2-stage lexicographic argmin within the 4-lane group ----
    #pragma unroll
    for (int off = 1; off <= 2; off <<= 1) {
        float ov = __shfl_xor_sync(FULL, best, off);
        int   oi = __shfl_xor_sync(FULL, bi,   off);
        if (ov < best || (ov == best && oi < bi)) { best = ov; bi = oi; }
    }

    if (sub == 0 && active) {
        float nb = (float)nbmod[it];
        out[row] = ((float)bi - 1.0f) / (nb - 1.0f) + 1.0f;
    }
}

extern "C" void kernel_launch(void* const* d_in, const int* in_sizes, int n_in,
                              void* d_out, int out_size) {
    const int*   user_ids    = (const int*)  d_in[0];
    const int*   item_ids    = (const int*)  d_in[1];
    const int*   concept_ids = (const int*)  d_in[2];
    const float* uemb        = (const float*)d_in[3];
    const float* irw         = (const float*)d_in[4];
    const float* W           = (const float*)d_in[5];
    const float* maskt       = (const float*)d_in[6];
    const int*   nbmod       = (const int*)  d_in[7];
    float* out = (float*)d_out;
    int nrows = in_sizes[0];

    gmat_kernel<<<CONCEPTS, 32>>>(W);

    int warps = (nrows + 7) / 8;          // 8 rows per warp
    int blocks = (warps + 7) / 8;         // 256 threads = 8 warps
    impact_kernel<<<blocks, 256>>>(
        user_ids, item_ids, concept_ids, uemb, irw, W, maskt, nbmod, out, nrows);
}

// round 8
// speedup vs baseline: 2.7982x; 2.7982x over previous
#include <cuda_runtime.h>

#define CONCEPTS 128
#define MM 14          // nb_mod_max + 2
#define DC 128         // concept dim
#define DIN 3

// Per-concept Gram G = W[c] W[c]^T, padded to 8 floats: {G00,G01,G02,G11,G12,G22,_,_}
__device__ float g_G[CONCEPTS * 8];

__device__ __forceinline__ unsigned redux_min_u32(unsigned v, unsigned mask) {
    unsigned r;
    asm volatile("redux.sync.min.u32 %0, %1, %2;" : "=r"(r) : "r"(v), "r"(mask));
    return r;
}

// ---------------------------------------------------------------------------
// G[c] = W[c] W[c]^T. One warp per concept.
// ---------------------------------------------------------------------------
__global__ void gmat_kernel(const float* __restrict__ W) {
    int c = blockIdx.x;
    int lane = threadIdx.x;
    const float4* w = reinterpret_cast<const float4*>(W + (size_t)c * DIN * DC);
    float4 a = w[lane];
    float4 b = w[32 + lane];
    float4 d = w[64 + lane];
    float s[6];
    s[0] = a.x*a.x + a.y*a.y + a.z*a.z + a.w*a.w;
    s[1] = a.x*b.x + a.y*b.y + a.z*b.z + a.w*b.w;
    s[2] = a.x*d.x + a.y*d.y + a.z*d.z + a.w*d.w;
    s[3] = b.x*b.x + b.y*b.y + b.z*b.z + b.w*b.w;
    s[4] = b.x*d.x + b.y*d.y + b.z*d.z + b.w*d.w;
    s[5] = d.x*d.x + d.y*d.y + d.z*d.z + d.w*d.w;
    #pragma unroll
    for (int off = 16; off; off >>= 1)
        #pragma unroll
        for (int k = 0; k < 6; k++)
            s[k] += __shfl_xor_sync(0xffffffffu, s[k], off);
    if (lane == 0) {
        #pragma unroll
        for (int k = 0; k < 6; k++) g_G[c * 8 + k] = s[k];
        g_G[c * 8 + 6] = 0.0f;
        g_G[c * 8 + 7] = 0.0f;
    }
}

// ---------------------------------------------------------------------------
// 2 rows per warp, 16 lanes per row (R3 layout — wavefront-optimal).
//   - mask gather replaced by validity predicate from nbmod (mask==0 iff 1<=m<=nb)
//   - argmin: float->orderable-u32, truncate to 28 bits, pack lane in low 4,
//     single redux.sync.min.u32 per half  (first-index tie-break preserved)
// ---------------------------------------------------------------------------
__global__ void __launch_bounds__(256) impact_kernel(
    const int*   __restrict__ user_ids,
    const int*   __restrict__ item_ids,
    const int*   __restrict__ concept_ids,
    const float* __restrict__ uemb,     // (USER_N, 128)
    const float* __restrict__ irw,      // (ITEM_N*14, 3)
    const float* __restrict__ W,        // (128, 3, 128)
    const float* __restrict__ maskt,    // (ITEM_N, 14)  [unused — derived from nbmod]
    const int*   __restrict__ nbmod,    // (ITEM_N,)
    float*       __restrict__ out,
    int nrows)
{
    const unsigned FULL = 0xffffffffu;
    int warp = (int)((blockIdx.x * blockDim.x + threadIdx.x) >> 5);
    int lane = threadIdx.x & 31;
    int half = lane >> 4;
    int hl   = lane & 15;
    unsigned hmask = 0xFFFFu << (half * 16);

    long row = (long)warp * 2 + half;
    bool active = row < nrows;
    long ridx = active ? row : 0;

    int uid = user_ids[ridx];
    int it  = item_ids[ridx];
    int cc  = concept_ids[ridx];
    int nb  = nbmod[it];                 // broadcast within half (1 line)

    // ---- gathers (coalesced float4: each half covers 2 contiguous lines) ----
    const float* ub = uemb + (size_t)uid * DC;
    float4 ua = __ldcs(reinterpret_cast<const float4*>(ub + 4 * hl));
    float4 uc = __ldcs(reinterpret_cast<const float4*>(ub + 64 + 4 * hl));

    const float* wb = W + (size_t)cc * DIN * DC;
    float4 w0a = *reinterpret_cast<const float4*>(wb + 4 * hl);
    float4 w0b = *reinterpret_cast<const float4*>(wb + 64 + 4 * hl);
    float4 w1a = *reinterpret_cast<const float4*>(wb + DC + 4 * hl);
    float4 w1b = *reinterpret_cast<const float4*>(wb + DC + 64 + 4 * hl);
    float4 w2a = *reinterpret_cast<const float4*>(wb + 2 * DC + 4 * hl);
    float4 w2b = *reinterpret_cast<const float4*>(wb + 2 * DC + 64 + 4 * hl);

    // item-response vectors: issue early (independent of the dot chain)
    float e0 = 0.f, e1 = 0.f, e2 = 0.f;
    bool valid = (hl >= 1) & (hl <= nb);   // == (mask[it][hl] == 0), hl<=12<MM
    if (hl < MM) {
        const float* e = irw + ((size_t)it * MM + hl) * DIN;
        e0 = e[0]; e1 = e[1]; e2 = e[2];
    }
    const float4* Gp = reinterpret_cast<const float4*>(g_G + cc * 8);
    float4 Ga = __ldg(Gp);        // G00 G01 G02 G11
    float4 Gb = __ldg(Gp + 1);    // G12 G22 _ _

    float v0 = ua.x*w0a.x + ua.y*w0a.y + ua.z*w0a.z + ua.w*w0a.w
             + uc.x*w0b.x + uc.y*w0b.y + uc.z*w0b.z + uc.w*w0b.w;
    float v1 = ua.x*w1a.x + ua.y*w1a.y + ua.z*w1a.z + ua.w*w1a.w
             + uc.x*w1b.x + uc.y*w1b.y + uc.z*w1b.z + uc.w*w1b.w;
    float v2 = ua.x*w2a.x + ua.y*w2a.y + ua.z*w2a.z + ua.w*w2a.w
             + uc.x*w2b.x + uc.y*w2b.y + uc.z*w2b.z + uc.w*w2b.w;

    // 4-stage butterfly all-reduce within each 16-lane half
    #pragma unroll
    for (int off = 8; off; off >>= 1) {
        v0 += __shfl_xor_sync(FULL, v0, off);
        v1 += __shfl_xor_sync(FULL, v1, off);
        v2 += __shfl_xor_sync(FULL, v2, off);
    }

    // ---- score: q - 2 e.v  (mask term is 0 on valid lanes) ----
    float score = __int_as_float(0x7f800000);   // +inf for invalid lanes
    if (valid) {
        float q = e0*e0*Ga.x + e1*e1*Ga.w + e2*e2*Gb.y
                + 2.0f*(e0*e1*Ga.y + e0*e2*Ga.z + e1*e2*Gb.x);
        score = q - 2.0f*(e0*v0 + e1*v1 + e2*v2);
    }

    // ---- argmin: orderable-u32 key, index packed in low 4 bits ----
    unsigned sb  = __float_as_uint(score);
    unsigned key = ((int)sb >= 0) ? (sb | 0x80000000u) : ~sb;   // monotone map
    unsigned packed = (key & 0xFFFFFFF0u) | (unsigned)hl;
    unsigned mnp = redux_min_u32(packed, hmask);
    int bi = (int)(mnp & 0xFu);

    if (hl == 0 && active) {
        out[row] = ((float)bi - 1.0f) / ((float)nb - 1.0f) + 1.0f;
    }
}

extern "C" void kernel_launch(void* const* d_in, const int* in_sizes, int n_in,
                              void* d_out, int out_size) {
    const int*   user_ids    = (const int*)  d_in[0];
    const int*   item_ids    = (const int*)  d_in[1];
    const int*   concept_ids = (const int*)  d_in[2];
    const float* uemb        = (const float*)d_in[3];
    const float* irw         = (const float*)d_in[4];
    const float* W           = (const float*)d_in[5];
    const float* maskt       = (const float*)d_in[6];
    const int*   nbmod       = (const int*)  d_in[7];
    float* out = (float*)d_out;
    int nrows = in_sizes[0];

    gmat_kernel<<<CONCEPTS, 32>>>(W);

    int warps = (nrows + 1) / 2;          // 2 rows per warp
    int blocks = (warps + 7) / 8;         // 256 threads = 8 warps
    impact_kernel<<<blocks, 256>>>(
        user_ids, item_ids, concept_ids, uemb, irw, W, maskt, nbmod, out, nrows);
}

// round 9
// speedup vs baseline: 2.8418x; 1.0156x over previous
#include <cuda_runtime.h>

#define CONCEPTS 128
#define MM 14          // nb_mod_max + 2
#define DC 128         // concept dim
#define DIN 3

// Per-concept Gram G = W[c] W[c]^T, padded to 8 floats: {G00,G01,G02,G11,G12,G22,_,_}
__device__ float g_G[CONCEPTS * 8];

__device__ __forceinline__ unsigned redux_min_u32(unsigned v, unsigned mask) {
    unsigned r;
    asm volatile("redux.sync.min.u32 %0, %1, %2;" : "=r"(r) : "r"(v), "r"(mask));
    return r;
}

// ---------------------------------------------------------------------------
// G[c] = W[c] W[c]^T. One warp per concept.
// ---------------------------------------------------------------------------
__global__ void gmat_kernel(const float* __restrict__ W) {
    int c = blockIdx.x;
    int lane = threadIdx.x;
    const float4* w = reinterpret_cast<const float4*>(W + (size_t)c * DIN * DC);
    float4 a = w[lane];
    float4 b = w[32 + lane];
    float4 d = w[64 + lane];
    float s[6];
    s[0] = a.x*a.x + a.y*a.y + a.z*a.z + a.w*a.w;
    s[1] = a.x*b.x + a.y*b.y + a.z*b.z + a.w*b.w;
    s[2] = a.x*d.x + a.y*d.y + a.z*d.z + a.w*d.w;
    s[3] = b.x*b.x + b.y*b.y + b.z*b.z + b.w*b.w;
    s[4] = b.x*d.x + b.y*d.y + b.z*d.z + b.w*d.w;
    s[5] = d.x*d.x + d.y*d.y + d.z*d.z + d.w*d.w;
    #pragma unroll
    for (int off = 16; off; off >>= 1)
        #pragma unroll
        for (int k = 0; k < 6; k++)
            s[k] += __shfl_xor_sync(0xffffffffu, s[k], off);
    if (lane == 0) {
        #pragma unroll
        for (int k = 0; k < 6; k++) g_G[c * 8 + k] = s[k];
        g_G[c * 8 + 6] = 0.0f;
        g_G[c * 8 + 7] = 0.0f;
    }
}

// ---------------------------------------------------------------------------
// 4 rows per warp; 8 lanes per row (grp = lane>>3, sub = lane&7).
// Per LDG.128: 4 rows x 128B contiguous = 4 full lines (wavefront-optimal).
//   - dots accumulated over 4 chunks of 4 channels per lane
//   - v all-reduce: 3-stage butterfly within 8-lane group
//   - each lane scores m = sub and m = sub+8 (serial, FMA pipe), local <= keeps
//     the smaller m; cross-lane argmin via packed-key redux.sync.min.u32
// ---------------------------------------------------------------------------
__global__ void __launch_bounds__(256) impact_kernel(
    const int*   __restrict__ user_ids,
    const int*   __restrict__ item_ids,
    const int*   __restrict__ concept_ids,
    const float* __restrict__ uemb,     // (USER_N, 128)
    const float* __restrict__ irw,      // (ITEM_N*14, 3)
    const float* __restrict__ W,        // (128, 3, 128)
    const float* __restrict__ maskt,    // (ITEM_N, 14)  [unused — derived from nbmod]
    const int*   __restrict__ nbmod,    // (ITEM_N,)
    float*       __restrict__ out,
    int nrows)
{
    const unsigned FULL = 0xffffffffu;
    int warp = (int)((blockIdx.x * blockDim.x + threadIdx.x) >> 5);
    int lane = threadIdx.x & 31;
    int grp  = lane >> 3;       // 0..3: which row in this warp
    int sub  = lane & 7;        // 0..7: lane within row group
    unsigned gmask = 0xFFu << (grp * 8);

    long row = (long)warp * 4 + grp;
    bool active = row < nrows;
    long ridx = active ? row : 0;

    int uid = user_ids[ridx];
    int it  = item_ids[ridx];
    int cc  = concept_ids[ridx];
    int nb  = nbmod[it];

    const float* ub = uemb + (size_t)uid * DC;
    const float* wb = W + (size_t)cc * DIN * DC;

    // ---- item-response vectors for this lane's two modalities (issue early) ----
    int m2 = sub + 8;
    const float* ebase = irw + (size_t)it * MM * DIN;
    float f0 = 0.f, f1 = 0.f, f2 = 0.f;   // e for m = sub
    float g0 = 0.f, g1 = 0.f, g2 = 0.f;   // e for m = sub+8
    {
        const float* e1p = ebase + sub * DIN;
        f0 = e1p[0]; f1 = e1p[1]; f2 = e1p[2];
        if (m2 < MM) {
            const float* e2p = ebase + m2 * DIN;
            g0 = e2p[0]; g1 = e2p[1]; g2 = e2p[2];
        }
    }
    const float4* Gp = reinterpret_cast<const float4*>(g_G + cc * 8);
    float4 Ga = __ldg(Gp);        // G00 G01 G02 G11
    float4 Gb = __ldg(Gp + 1);    // G12 G22 _ _

    // ---- dot products: 4 chunks x 4 channels per lane ----
    float v0 = 0.f, v1 = 0.f, v2 = 0.f;
    #pragma unroll
    for (int k = 0; k < 4; k++) {
        int off = k * 32 + sub * 4;
        float4 u4 = __ldcs(reinterpret_cast<const float4*>(ub + off));
        float4 a0 = *reinterpret_cast<const float4*>(wb + off);
        float4 a1 = *reinterpret_cast<const float4*>(wb + DC + off);
        float4 a2 = *reinterpret_cast<const float4*>(wb + 2 * DC + off);
        v0 += u4.x*a0.x + u4.y*a0.y + u4.z*a0.z + u4.w*a0.w;
        v1 += u4.x*a1.x + u4.y*a1.y + u4.z*a1.z + u4.w*a1.w;
        v2 += u4.x*a2.x + u4.y*a2.y + u4.z*a2.z + u4.w*a2.w;
    }

    // ---- 3-stage all-reduce within the 8-lane group ----
    #pragma unroll
    for (int off = 4; off; off >>= 1) {
        v0 += __shfl_xor_sync(FULL, v0, off);
        v1 += __shfl_xor_sync(FULL, v1, off);
        v2 += __shfl_xor_sync(FULL, v2, off);
    }

    // ---- score both modalities; keep smaller m on ties ----
    const float INF = __int_as_float(0x7f800000);
    bool valid1 = (sub >= 1) & (sub <= nb);       // m = sub  (sub<=7 < MM)
    bool valid2 = (m2 <= nb);                     // m = sub+8 (nb<=12 so m2<=12<MM ok)
    float best = INF;
    int   bm   = 15;
    if (valid2) {
        float q = g0*g0*Ga.x + g1*g1*Ga.w + g2*g2*Gb.y
                + 2.0f*(g0*g1*Ga.y + g0*g2*Ga.z + g1*g2*Gb.x);
        best = q - 2.0f*(g0*v0 + g1*v1 + g2*v2);
        bm = m2;
    }
    if (valid1) {
        float q = f0*f0*Ga.x + f1*f1*Ga.w + f2*f2*Gb.y
                + 2.0f*(f0*f1*Ga.y + f0*f2*Ga.z + f1*f2*Gb.x);
        float s = q - 2.0f*(f0*v0 + f1*v1 + f2*v2);
        if (s <= best) { best = s; bm = sub; }    // <=: smaller m wins ties
    }

    // ---- cross-lane argmin: orderable key, m in low 4 bits ----
    unsigned sb  = __float_as_uint(best);
    unsigned key = ((int)sb >= 0) ? (sb | 0x80000000u) : ~sb;
    unsigned packed = (key & 0xFFFFFFF0u) | (unsigned)bm;
    unsigned mnp = redux_min_u32(packed, gmask);
    int bi = (int)(mnp & 0xFu);

    if (sub == 0 && active) {
        out[row] = ((float)bi - 1.0f) / ((float)nb - 1.0f) + 1.0f;
    }
}

extern "C" void kernel_launch(void* const* d_in, const int* in_sizes, int n_in,
                              void* d_out, int out_size) {
    const int*   user_ids    = (const int*)  d_in[0];
    const int*   item_ids    = (const int*)  d_in[1];
    const int*   concept_ids = (const int*)  d_in[2];
    const float* uemb        = (const float*)d_in[3];
    const float* irw         = (const float*)d_in[4];
    const float* W           = (const float*)d_in[5];
    const float* maskt       = (const float*)d_in[6];
    const int*   nbmod       = (const int*)  d_in[7];
    float* out = (float*)d_out;
    int nrows = in_sizes[0];

    gmat_kernel<<<CONCEPTS, 32>>>(W);

    int warps = (nrows + 3) / 4;          // 4 rows per warp
    int blocks = (warps + 7) / 8;         // 256 threads = 8 warps
    impact_kernel<<<blocks, 256>>>(
        user_ids, item_ids, concept_ids, uemb, irw, W, maskt, nbmod, out, nrows);
}